// round 1
// baseline (speedup 1.0000x reference)
#include <cuda_runtime.h>
#include <math.h>

#define N_   4096
#define E_   131072
#define FEAT_ 64
#define HID_ 256
#define NEG_ (-1e9f)

__device__ float g_h0 [N_*HID_];
__device__ float g_x  [N_*HID_];
__device__ float g_hl [N_*HID_];
__device__ float g_xg [N_*HID_];
__device__ float g_sup[N_*2*HID_];
__device__ float g_q  [N_*HID_];
__device__ float g_k  [N_*HID_];
__device__ float g_v  [N_*HID_];
__device__ float g_hms[N_*HID_];
__device__ float g_S  [(size_t)N_*N_];
__device__ float g_el [N_*4];
__device__ float g_er [N_*4];
__device__ float g_y  [N_];
__device__ float g_xyz0[N_*3];
__device__ float g_xyz1[N_*3];
__device__ int   g_cnt[N_];
__device__ int   g_rowptr[N_+1];
__device__ int   g_cur[N_];
__device__ int   g_psrc[E_];
__device__ int   g_maskmode;

__global__ void detect_mask_mode(const unsigned int* __restrict__ m) {
    bool allbin = true, anyfloat = false;
    for (int i = 0; i < 1024; i++) {
        unsigned int w = m[i];
        if (w == 0x3f800000u) anyfloat = true;
        if (w > 1u) allbin = false;
    }
    g_maskmode = anyfloat ? 2 : (allbin ? 1 : 0);
}

__device__ __forceinline__ bool mask_at(const void* p, size_t i, int mode) {
    if (mode == 0) return ((const unsigned char*)p)[i] != 0;
    if (mode == 1) return ((const int*)p)[i] != 0;
    return ((const float*)p)[i] != 0.0f;
}

__global__ void sgemm64(const float* __restrict__ A, const float* __restrict__ B,
                        float* __restrict__ C, float* __restrict__ C2,
                        int M, int Nc, int K,
                        const float* __restrict__ bias, int relu, float cacc,
                        const float* __restrict__ X1, float c1,
                        const float* __restrict__ X2, float c2,
                        const float* __restrict__ X3, float c3)
{
    __shared__ __align__(16) float As[16][68];
    __shared__ __align__(16) float Bs[16][68];
    const int t  = threadIdx.x;
    const int tx = t & 15, ty = t >> 4;
    const int m0 = blockIdx.y * 64, n0 = blockIdx.x * 64;
    const int ra = t >> 2, kq = t & 3;
    const int kr = t >> 4, nq = t & 15;

    float acc[4][4] = {};
    for (int k0 = 0; k0 < K; k0 += 16) {
        float4 a = *(const float4*)&A[(size_t)(m0 + ra) * K + k0 + kq * 4];
        As[kq*4+0][ra] = a.x; As[kq*4+1][ra] = a.y; As[kq*4+2][ra] = a.z; As[kq*4+3][ra] = a.w;
        float4 b = *(const float4*)&B[(size_t)(k0 + kr) * Nc + n0 + nq * 4];
        *(float4*)&Bs[kr][nq*4] = b;
        __syncthreads();
#pragma unroll
        for (int kk = 0; kk < 16; kk++) {
            float4 av = *(float4*)&As[kk][ty*4];
            float4 bv = *(float4*)&Bs[kk][tx*4];
            acc[0][0]=fmaf(av.x,bv.x,acc[0][0]); acc[0][1]=fmaf(av.x,bv.y,acc[0][1]);
            acc[0][2]=fmaf(av.x,bv.z,acc[0][2]); acc[0][3]=fmaf(av.x,bv.w,acc[0][3]);
            acc[1][0]=fmaf(av.y,bv.x,acc[1][0]); acc[1][1]=fmaf(av.y,bv.y,acc[1][1]);
            acc[1][2]=fmaf(av.y,bv.z,acc[1][2]); acc[1][3]=fmaf(av.y,bv.w,acc[1][3]);
            acc[2][0]=fmaf(av.z,bv.x,acc[2][0]); acc[2][1]=fmaf(av.z,bv.y,acc[2][1]);
            acc[2][2]=fmaf(av.z,bv.z,acc[2][2]); acc[2][3]=fmaf(av.z,bv.w,acc[2][3]);
            acc[3][0]=fmaf(av.w,bv.x,acc[3][0]); acc[3][1]=fmaf(av.w,bv.y,acc[3][1]);
            acc[3][2]=fmaf(av.w,bv.z,acc[3][2]); acc[3][3]=fmaf(av.w,bv.w,acc[3][3]);
        }
        __syncthreads();
    }
#pragma unroll
    for (int i = 0; i < 4; i++) {
        int m = m0 + ty*4 + i;
#pragma unroll
        for (int j = 0; j < 4; j++) {
            int n = n0 + tx*4 + j;
            size_t idx = (size_t)m * Nc + n;
            float v = cacc * acc[i][j];
            if (bias) v += bias[n];
            if (X1) v += c1 * X1[idx];
            if (X2) v += c2 * X2[idx];
            if (X3) v += c3 * X3[idx];
            if (relu) v = fmaxf(v, 0.0f);
            C[idx] = v;
            if (C2) C2[idx] = v;
        }
    }
}

__global__ void scores_kernel(const float* __restrict__ Q, const float* __restrict__ Km,
                              const float* __restrict__ xyz,
                              const void* __restrict__ dmask, const void* __restrict__ bmask,
                              float* __restrict__ S)
{
    __shared__ __align__(16) float Qs[16][68];
    __shared__ __align__(16) float Ks[16][68];
    __shared__ float xi[64][3], xj[64][3], sqi[64], sqj[64], yi[64], yj[64];
    const int t  = threadIdx.x;
    const int i0 = blockIdx.y * 64, j0 = blockIdx.x * 64;
    if (t < 64) {
        float a = xyz[(i0+t)*3+0], b = xyz[(i0+t)*3+1], c = xyz[(i0+t)*3+2];
        xi[t][0]=a; xi[t][1]=b; xi[t][2]=c;
        sqi[t] = fmaf(c,c,fmaf(b,b,a*a));
        yi[t]  = g_y[i0+t];
    } else if (t < 128) {
        int u = t - 64;
        float a = xyz[(j0+u)*3+0], b = xyz[(j0+u)*3+1], c = xyz[(j0+u)*3+2];
        xj[u][0]=a; xj[u][1]=b; xj[u][2]=c;
        sqj[u] = fmaf(c,c,fmaf(b,b,a*a));
        yj[u]  = g_y[j0+u];
    }
    const int ra = t >> 2, kq = t & 3;
    const int tx = t & 15, ty = t >> 4;
    float acc[4][4] = {};
    for (int k0 = 0; k0 < HID_; k0 += 16) {
        float4 a = *(const float4*)&Q [(size_t)(i0 + ra) * HID_ + k0 + kq * 4];
        float4 b = *(const float4*)&Km[(size_t)(j0 + ra) * HID_ + k0 + kq * 4];
        Qs[kq*4+0][ra]=a.x; Qs[kq*4+1][ra]=a.y; Qs[kq*4+2][ra]=a.z; Qs[kq*4+3][ra]=a.w;
        Ks[kq*4+0][ra]=b.x; Ks[kq*4+1][ra]=b.y; Ks[kq*4+2][ra]=b.z; Ks[kq*4+3][ra]=b.w;
        __syncthreads();
#pragma unroll
        for (int kk = 0; kk < 16; kk++) {
            float4 av = *(float4*)&Qs[kk][ty*4];
            float4 bv = *(float4*)&Ks[kk][tx*4];
            acc[0][0]=fmaf(av.x,bv.x,acc[0][0]); acc[0][1]=fmaf(av.x,bv.y,acc[0][1]);
            acc[0][2]=fmaf(av.x,bv.z,acc[0][2]); acc[0][3]=fmaf(av.x,bv.w,acc[0][3]);
            acc[1][0]=fmaf(av.y,bv.x,acc[1][0]); acc[1][1]=fmaf(av.y,bv.y,acc[1][1]);
            acc[1][2]=fmaf(av.y,bv.z,acc[1][2]); acc[1][3]=fmaf(av.y,bv.w,acc[1][3]);
            acc[2][0]=fmaf(av.z,bv.x,acc[2][0]); acc[2][1]=fmaf(av.z,bv.y,acc[2][1]);
            acc[2][2]=fmaf(av.z,bv.z,acc[2][2]); acc[2][3]=fmaf(av.z,bv.w,acc[2][3]);
            acc[3][0]=fmaf(av.w,bv.x,acc[3][0]); acc[3][1]=fmaf(av.w,bv.y,acc[3][1]);
            acc[3][2]=fmaf(av.w,bv.z,acc[3][2]); acc[3][3]=fmaf(av.w,bv.w,acc[3][3]);
        }
        __syncthreads();
    }
    const int mode = g_maskmode;
#pragma unroll
    for (int i = 0; i < 4; i++) {
        int li = ty*4 + i, gi = i0 + li;
#pragma unroll
        for (int j = 0; j < 4; j++) {
            int lj = tx*4 + j, gj = j0 + lj;
            size_t idx = (size_t)gi * N_ + gj;
            float dot = fmaf(xi[li][2], xj[lj][2], fmaf(xi[li][1], xj[lj][1], xi[li][0]*xj[lj][0]));
            float dist2 = (sqi[li] + sqj[lj]) - 2.0f * dot;
            bool ok = mask_at(dmask, idx, mode) && mask_at(bmask, idx, mode) && (dist2 <= 100.0f);
            float sc = ok ? (acc[i][j] * 0.0625f - fabsf(yi[li] - yj[lj])) : NEG_;
            S[idx] = sc;
        }
    }
}

__global__ void softmax_rows(float* __restrict__ S)
{
    __shared__ float red[256];
    const int row = blockIdx.x, t = threadIdx.x;
    float* p = S + (size_t)row * N_;
    float4 v[4];
    float mx = -1e30f;
#pragma unroll
    for (int c = 0; c < 4; c++) {
        v[c] = *(float4*)&p[c*1024 + t*4];
        mx = fmaxf(mx, fmaxf(fmaxf(v[c].x, v[c].y), fmaxf(v[c].z, v[c].w)));
    }
    red[t] = mx; __syncthreads();
    for (int s = 128; s > 0; s >>= 1) { if (t < s) red[t] = fmaxf(red[t], red[t+s]); __syncthreads(); }
    mx = red[0]; __syncthreads();
    float sum = 0.0f;
#pragma unroll
    for (int c = 0; c < 4; c++) {
        v[c].x = expf(v[c].x - mx); v[c].y = expf(v[c].y - mx);
        v[c].z = expf(v[c].z - mx); v[c].w = expf(v[c].w - mx);
        sum += v[c].x + v[c].y + v[c].z + v[c].w;
    }
    red[t] = sum; __syncthreads();
    for (int s = 128; s > 0; s >>= 1) { if (t < s) red[t] += red[t+s]; __syncthreads(); }
    float inv = 1.0f / red[0];
#pragma unroll
    for (int c = 0; c < 4; c++) {
        v[c].x *= inv; v[c].y *= inv; v[c].z *= inv; v[c].w *= inv;
        *(float4*)&p[c*1024 + t*4] = v[c];
    }
}

__global__ void attn_xyz_k(const float* __restrict__ S, const float* __restrict__ xyz,
                           float* __restrict__ out)
{
    __shared__ float r0[256], r1[256], r2[256];
    const int row = blockIdx.x, t = threadIdx.x;
    const float* p = S + (size_t)row * N_;
    float a0 = 0.f, a1 = 0.f, a2 = 0.f;
    for (int j = t; j < N_; j += 256) {
        float a = p[j];
        a0 = fmaf(a, xyz[j*3+0], a0);
        a1 = fmaf(a, xyz[j*3+1], a1);
        a2 = fmaf(a, xyz[j*3+2], a2);
    }
    r0[t]=a0; r1[t]=a1; r2[t]=a2; __syncthreads();
    for (int s = 128; s > 0; s >>= 1) {
        if (t < s) { r0[t]+=r0[t+s]; r1[t]+=r1[t+s]; r2[t]+=r2[t+s]; }
        __syncthreads();
    }
    if (t == 0) { out[row*3+0]=r0[0]; out[row*3+1]=r1[0]; out[row*3+2]=r2[0]; }
}

__global__ void compute_elr(const float* __restrict__ hl, const float* __restrict__ al,
                            const float* __restrict__ ar)
{
    int idx = blockIdx.x * blockDim.x + threadIdx.x;
    if (idx >= N_*4) return;
    int node = idx >> 2, h = idx & 3;
    const float* row = hl + (size_t)node * HID_ + h * 64;
    float sl = 0.f, sr = 0.f;
#pragma unroll 8
    for (int d = 0; d < 64; d++) {
        float v = row[d];
        sl = fmaf(v, al[h*64+d], sl);
        sr = fmaf(v, ar[h*64+d], sr);
    }
    g_el[idx] = sl; g_er[idx] = sr;
}

__global__ void zero_cnt() { int i = blockIdx.x*blockDim.x + threadIdx.x; if (i < N_) g_cnt[i] = 0; }
__global__ void count_edges(const int* __restrict__ dst) {
    int e = blockIdx.x*blockDim.x + threadIdx.x; if (e < E_) atomicAdd(&g_cnt[dst[e]], 1);
}
__global__ void scan4096() {
    __shared__ int part[1024];
    int t = threadIdx.x, base = t * 4;
    int a0 = g_cnt[base], a1 = g_cnt[base+1], a2 = g_cnt[base+2], a3 = g_cnt[base+3];
    int s = a0 + a1 + a2 + a3;
    part[t] = s; __syncthreads();
    for (int off = 1; off < 1024; off <<= 1) {
        int v = (t >= off) ? part[t-off] : 0;
        __syncthreads();
        part[t] += v;
        __syncthreads();
    }
    int excl = part[t] - s;
    g_rowptr[base+0] = excl;           g_cur[base+0] = excl;
    g_rowptr[base+1] = excl+a0;        g_cur[base+1] = excl+a0;
    g_rowptr[base+2] = excl+a0+a1;     g_cur[base+2] = excl+a0+a1;
    g_rowptr[base+3] = excl+a0+a1+a2;  g_cur[base+3] = excl+a0+a1+a2;
    if (t == 1023) g_rowptr[4096] = part[1023];
}
__global__ void scatter_edges(const int* __restrict__ src, const int* __restrict__ dst) {
    int e = blockIdx.x*blockDim.x + threadIdx.x;
    if (e < E_) { int p = atomicAdd(&g_cur[dst[e]], 1); g_psrc[p] = src[e]; }
}

__global__ void gat_aggregate(const float* __restrict__ hl, float* __restrict__ xg)
{
    const int node = (blockIdx.x * blockDim.x + threadIdx.x) >> 5;
    const int lane = threadIdx.x & 31;
    if (node >= N_) return;
    const int beg = g_rowptr[node], end = g_rowptr[node+1];
    const float er_i = (lane < 4) ? g_er[node*4 + lane] : 0.f;
    float m = -1e30f;
    for (int p = beg; p < end; p++) {
        int s = g_psrc[p];
        if (lane < 4) {
            float v = g_el[s*4 + lane] + er_i;
            float e = (v > 0.f) ? v : 0.2f * v;
            m = fmaxf(m, e);
        }
    }
    float m0 = __shfl_sync(0xffffffffu, m, 0), m1 = __shfl_sync(0xffffffffu, m, 1);
    float m2 = __shfl_sync(0xffffffffu, m, 2), m3 = __shfl_sync(0xffffffffu, m, 3);
    const int myh = lane >> 3;
    float4 acc0 = {0,0,0,0}, acc1 = {0,0,0,0};
    float z = 0.f;
    for (int p = beg; p < end; p++) {
        int s = g_psrc[p];
        float w = 0.f;
        if (lane < 4) {
            float v = g_el[s*4 + lane] + er_i;
            float e = (v > 0.f) ? v : 0.2f * v;
            float mm = (lane==0)?m0:(lane==1)?m1:(lane==2)?m2:m3;
            w = expf(e - mm);
            z += w;
        }
        float w0 = __shfl_sync(0xffffffffu, w, 0), w1 = __shfl_sync(0xffffffffu, w, 1);
        float w2 = __shfl_sync(0xffffffffu, w, 2), w3 = __shfl_sync(0xffffffffu, w, 3);
        float wm = (myh==0)?w0:(myh==1)?w1:(myh==2)?w2:w3;
        const float4* hp = (const float4*)(hl + (size_t)s * HID_ + lane * 8);
        float4 hv0 = hp[0], hv1 = hp[1];
        acc0.x=fmaf(wm,hv0.x,acc0.x); acc0.y=fmaf(wm,hv0.y,acc0.y);
        acc0.z=fmaf(wm,hv0.z,acc0.z); acc0.w=fmaf(wm,hv0.w,acc0.w);
        acc1.x=fmaf(wm,hv1.x,acc1.x); acc1.y=fmaf(wm,hv1.y,acc1.y);
        acc1.z=fmaf(wm,hv1.z,acc1.z); acc1.w=fmaf(wm,hv1.w,acc1.w);
    }
    float z0 = __shfl_sync(0xffffffffu, z, 0), z1 = __shfl_sync(0xffffffffu, z, 1);
    float z2 = __shfl_sync(0xffffffffu, z, 2), z3 = __shfl_sync(0xffffffffu, z, 3);
    float zm = (myh==0)?z0:(myh==1)?z1:(myh==2)?z2:z3;
    float inv = 1.0f / (zm + 1e-9f);
    acc0.x*=inv; acc0.y*=inv; acc0.z*=inv; acc0.w*=inv;
    acc1.x*=inv; acc1.y*=inv; acc1.z*=inv; acc1.w*=inv;
    float4* op = (float4*)(xg + (size_t)node * HID_ + lane * 8);
    op[0] = acc0; op[1] = acc1;
}

__global__ void pack_support(const float* __restrict__ xg, const float* __restrict__ h0,
                             float* __restrict__ sup)
{
    int i = blockIdx.x * blockDim.x + threadIdx.x;
    if (i >= N_ * 512) return;
    int r = i >> 9, c = i & 511;
    sup[i] = (c < 256) ? xg[(size_t)r*256 + c] : h0[(size_t)r*256 + (c-256)];
}

__global__ void yhat_k(const float* __restrict__ x, const float* __restrict__ W,
                       const float* __restrict__ b)
{
    int i = blockIdx.x * blockDim.x + threadIdx.x;
    if (i >= N_) return;
    const float* r = x + (size_t)i * HID_;
    float l0 = b[0], l1 = b[1];
#pragma unroll 8
    for (int d = 0; d < HID_; d++) {
        float v = r[d];
        l0 = fmaf(v, W[2*d+0], l0);
        l1 = fmaf(v, W[2*d+1], l1);
    }
    g_y[i] = 1.0f / (1.0f + expf(l0 - l1));
}

__global__ void cls_k(const float* __restrict__ x, const float* __restrict__ W,
                      const float* __restrict__ b, float* __restrict__ out)
{
    int i = blockIdx.x * blockDim.x + threadIdx.x;
    if (i >= N_) return;
    const float* r = x + (size_t)i * HID_;
    float l0 = b[0], l1 = b[1];
#pragma unroll 8
    for (int d = 0; d < HID_; d++) {
        float v = r[d];
        l0 = fmaf(v, W[2*d+0], l0);
        l1 = fmaf(v, W[2*d+1], l1);
    }
    out[2*i+0] = l0;
    out[2*i+1] = l1;
}

extern "C" void kernel_launch(void* const* d_in, const int* in_sizes, int n_in,
                              void* d_out, int out_size)
{
    const float* feat   = (const float*)d_in[0];
    const float* xyz_in = (const float*)d_in[1];
    const int*   src    = (const int*)  d_in[2];
    const int*   dst    = (const int*)  d_in[3];
    const void*  dmask  = d_in[4];
    const void*  bmask  = d_in[5];
    const float* fcW  = (const float*)d_in[6];
    const float* fcb  = (const float*)d_in[7];
    const float* gatW = (const float*)d_in[8];
    const float* al   = (const float*)d_in[9];
    const float* ar   = (const float*)d_in[10];
    const float* gcW  = (const float*)d_in[11];
    const float* cgW  = (const float*)d_in[12];
    const float* cgb  = (const float*)d_in[13];
    const float* qW   = (const float*)d_in[14];
    const float* qb   = (const float*)d_in[15];
    const float* kW   = (const float*)d_in[16];
    const float* kb   = (const float*)d_in[17];
    const float* vW   = (const float*)d_in[18];
    const float* vb   = (const float*)d_in[19];
    const float* oW   = (const float*)d_in[20];
    const float* ob   = (const float*)d_in[21];
    const float* clsW = (const float*)d_in[22];
    const float* clsb = (const float*)d_in[23];

    float *px, *ph0, *phl, *pxg, *psup, *pq, *pk, *pv, *phms, *pS, *pxyz0, *pxyz1;
    cudaGetSymbolAddress((void**)&px,    g_x);
    cudaGetSymbolAddress((void**)&ph0,   g_h0);
    cudaGetSymbolAddress((void**)&phl,   g_hl);
    cudaGetSymbolAddress((void**)&pxg,   g_xg);
    cudaGetSymbolAddress((void**)&psup,  g_sup);
    cudaGetSymbolAddress((void**)&pq,    g_q);
    cudaGetSymbolAddress((void**)&pk,    g_k);
    cudaGetSymbolAddress((void**)&pv,    g_v);
    cudaGetSymbolAddress((void**)&phms,  g_hms);
    cudaGetSymbolAddress((void**)&pS,    g_S);
    cudaGetSymbolAddress((void**)&pxyz0, g_xyz0);
    cudaGetSymbolAddress((void**)&pxyz1, g_xyz1);

    detect_mask_mode<<<1, 1>>>((const unsigned int*)dmask);

    sgemm64<<<dim3(HID_/64, N_/64), 256>>>(feat, fcW, px, ph0, N_, HID_, FEAT_,
                                           fcb, 1, 1.0f, nullptr,0.f, nullptr,0.f, nullptr,0.f);

    zero_cnt<<<N_/256, 256>>>();
    count_edges<<<E_/256, 256>>>(dst);
    scan4096<<<1, 1024>>>();
    scatter_edges<<<E_/256, 256>>>(src, dst);

    const float ALPHA = 0.1f, LAMDA = 0.5f;
    for (int l = 0; l < 4; l++) {
        sgemm64<<<dim3(HID_/64, N_/64), 256>>>(px, gatW + (size_t)l*HID_*HID_, phl, nullptr,
                                               N_, HID_, HID_, nullptr, 0, 1.0f,
                                               nullptr,0.f, nullptr,0.f, nullptr,0.f);
        compute_elr<<<(N_*4)/256, 256>>>(phl, al + l*4*64, ar + l*4*64);
        gat_aggregate<<<N_/8, 256>>>(phl, pxg);
        pack_support<<<(N_*512)/256, 256>>>(pxg, ph0, psup);
        float theta = fminf(1.0f, logf(LAMDA / (float)(l + 1) + 1.0f));
        sgemm64<<<dim3(HID_/64, N_/64), 256>>>(psup, gcW + (size_t)l*512*HID_, px, nullptr,
                                               N_, HID_, 512, nullptr, 0, theta,
                                               pxg, (1.0f-theta)*(1.0f-ALPHA),
                                               ph0, (1.0f-theta)*ALPHA,
                                               px,  1.0f);
    }

    yhat_k<<<N_/256, 256>>>(px, cgW, cgb);

    const float* xyz_cur = xyz_in;
    float* xyz_buf[2] = { pxyz0, pxyz1 };
    for (int l = 0; l < 4; l++) {
        sgemm64<<<dim3(HID_/64, N_/64), 256>>>(px, qW + (size_t)l*HID_*HID_, pq, nullptr,
                                               N_, HID_, HID_, qb + l*HID_, 0, 1.0f,
                                               nullptr,0.f, nullptr,0.f, nullptr,0.f);
        sgemm64<<<dim3(HID_/64, N_/64), 256>>>(px, kW + (size_t)l*HID_*HID_, pk, nullptr,
                                               N_, HID_, HID_, kb + l*HID_, 0, 1.0f,
                                               nullptr,0.f, nullptr,0.f, nullptr,0.f);
        sgemm64<<<dim3(HID_/64, N_/64), 256>>>(px, vW + (size_t)l*HID_*HID_, pv, nullptr,
                                               N_, HID_, HID_, vb + l*HID_, 0, 1.0f,
                                               nullptr,0.f, nullptr,0.f, nullptr,0.f);
        scores_kernel<<<dim3(N_/64, N_/64), 256>>>(pq, pk, xyz_cur, dmask, bmask, pS);
        softmax_rows<<<N_, 256>>>(pS);
        attn_xyz_k<<<N_, 256>>>(pS, xyz_cur, xyz_buf[l & 1]);
        sgemm64<<<dim3(HID_/64, N_/64), 256>>>(pS, pv, phms, nullptr, N_, HID_, N_,
                                               nullptr, 0, 1.0f,
                                               nullptr,0.f, nullptr,0.f, nullptr,0.f);
        sgemm64<<<dim3(HID_/64, N_/64), 256>>>(phms, oW + (size_t)l*HID_*HID_, px, nullptr,
                                               N_, HID_, HID_, ob + l*HID_, 0, 1.0f,
                                               px, 1.0f, nullptr,0.f, nullptr,0.f);
        xyz_cur = xyz_buf[l & 1];
    }

    cls_k<<<N_/256, 256>>>(px, clsW, clsb, (float*)d_out);
}